// round 2
// baseline (speedup 1.0000x reference)
#include <cuda_runtime.h>
#include <math.h>

#define EPSF 1e-6f

// Padded node table: up to 131072 nodes * 2 float4 = 4 MB static scratch.
__device__ float4 g_npad[131072 * 2];

__global__ void pad_nodes_kernel(const float* __restrict__ nodes, int n_nodes) {
    int i = blockIdx.x * blockDim.x + threadIdx.x;
    if (i < n_nodes) {
        const float* p = nodes + (size_t)i * 7;
        g_npad[i * 2 + 0] = make_float4(p[0], p[1], p[2], p[3]);
        g_npad[i * 2 + 1] = make_float4(p[4], p[5], p[6], 0.0f);
    }
}

__device__ __forceinline__ float3 f3cross(float3 a, float3 b) {
    return make_float3(a.y * b.z - a.z * b.y,
                       a.z * b.x - a.x * b.z,
                       a.x * b.y - a.y * b.x);
}

// _qrot: v + w*(2*cross(u,v)) + cross(u, 2*cross(u,v))
__device__ __forceinline__ float3 qrot(float4 q, float3 v) {
    float3 u = make_float3(q.x, q.y, q.z);
    float3 t = f3cross(u, v);
    t.x *= 2.0f; t.y *= 2.0f; t.z *= 2.0f;
    float3 c = f3cross(u, t);
    return make_float3(v.x + q.w * t.x + c.x,
                       v.y + q.w * t.y + c.y,
                       v.z + q.w * t.z + c.z);
}

__device__ __forceinline__ float4 qmul(float4 a, float4 b) {
    return make_float4(
        a.w * b.x + a.x * b.w + a.y * b.z - a.z * b.y,
        a.w * b.y - a.x * b.z + a.y * b.w + a.z * b.x,
        a.w * b.z + a.x * b.y - a.y * b.x + a.z * b.w,
        a.w * b.w - a.x * b.x - a.y * b.y - a.z * b.z);
}

__global__ __launch_bounds__(256)
void pose_graph_kernel(const int* __restrict__ edges,
                       const float* __restrict__ poses,
                       float* __restrict__ out,
                       int n_edges, int n_nodes)
{
    __shared__ int    sidx[512];   // [0..255]=node1 idx, [256..511]=node2 idx
    __shared__ float4 s0[512];     // first half (floats 0..3) of each gathered node
    __shared__ float4 s1[512];     // second half (floats 4..6, pad)
    __shared__ float  sbuf[1792];  // pose staging (256*7), reused for output (256*6)

    const int t  = threadIdx.x;
    const int e0 = blockIdx.x * 256;
    const int e  = e0 + t;
    const bool valid = (e < n_edges);
    const bool full  = (e0 + 256) <= n_edges;

    // ---- stage edge indices (coalesced LDG.64 over int2; edges are int32) ----
    {
        int i1 = 0, i2 = 0;
        if (valid) {
            const int2* E = (const int2*)edges;
            int2 v = __ldg(&E[e]);
            i1 = v.x; i2 = v.y;
        }
        // defensive clamp: out-of-range indices become visible as rel_err,
        // not as an illegal memory access
        i1 = min(max(i1, 0), n_nodes - 1);
        i2 = min(max(i2, 0), n_nodes - 1);
        sidx[t]       = i1;
        sidx[256 + t] = i2;
    }

    // ---- stage poses (vectorized when the block is full) ----
    if (full) {
        const float4* P4 = (const float4*)(poses + (size_t)e0 * 7); // 7168B/block, 16B aligned
        float4* S4 = (float4*)sbuf;
        int k0 = t;
        S4[k0] = __ldg(&P4[k0]);
        int k1 = t + 256;
        if (k1 < 448) S4[k1] = __ldg(&P4[k1]);
    } else {
        int nf = (n_edges - e0) * 7;
        for (int k = t; k < nf; k += 256) sbuf[k] = poses[(size_t)e0 * 7 + k];
    }
    __syncthreads();

    // ---- cooperative node gather: adjacent lanes fetch the two halves of
    //      the SAME node, so each LDG.128 touches ~16 cache lines, not 32 ----
#pragma unroll
    for (int j = 0; j < 4; j++) {
        int s = t + j * 256;       // 0..1023
        int n = s >> 1;            // node slot 0..511
        int h = s & 1;             // half 0/1
        int idx = sidx[n];
        float4 v = __ldg(&g_npad[idx * 2 + h]);
        if (h == 0) s0[n] = v; else s1[n] = v;
    }
    __syncthreads();

    // ---- per-edge SE(3) math ----
    float r0 = 0.f, r1 = 0.f, r2 = 0.f, r3 = 0.f, r4 = 0.f, r5 = 0.f;
    if (valid) {
        // pose
        float p0 = sbuf[t * 7 + 0], p1 = sbuf[t * 7 + 1], p2 = sbuf[t * 7 + 2];
        float p3 = sbuf[t * 7 + 3], p4 = sbuf[t * 7 + 4], p5 = sbuf[t * 7 + 5], p6 = sbuf[t * 7 + 6];
        // gathered nodes
        float4 n1a = s0[t],       n1b = s1[t];
        float4 n2a = s0[256 + t], n2b = s1[256 + t];

        float3 t1 = make_float3(n1a.x, n1a.y, n1a.z);
        float4 q1 = make_float4(n1a.w, n1b.x, n1b.y, n1b.z);
        float3 t2 = make_float3(n2a.x, n2a.y, n2a.z);
        float4 q2 = make_float4(n2a.w, n2b.x, n2b.y, n2b.z);

        // A = inv(pose)
        float4 qa = make_float4(-p3, -p4, -p5, p6);
        float3 tp = make_float3(p0, p1, p2);
        float3 ra = qrot(qa, tp);
        float3 ta = make_float3(-ra.x, -ra.y, -ra.z);

        // B = A * node2
        float3 rb = qrot(qa, t2);
        float3 tb = make_float3(ta.x + rb.x, ta.y + rb.y, ta.z + rb.z);
        float4 qb = qmul(qa, q2);

        // C = inv(node1)
        float4 qc = make_float4(-q1.x, -q1.y, -q1.z, q1.w);
        float3 rc = qrot(qc, t1);
        float3 tc = make_float3(-rc.x, -rc.y, -rc.z);

        // E = B * C
        float3 re = qrot(qb, tc);
        float3 te = make_float3(tb.x + re.x, tb.y + re.y, tb.z + re.z);
        float4 qe = qmul(qb, qc);

        // se3_log
        float nn = sqrtf(qe.x * qe.x + qe.y * qe.y + qe.z * qe.z);
        float scale;
        if (nn > EPSF) {
            scale = 2.0f * atan2f(nn, qe.w) / nn;
        } else {
            float dw = (fabsf(qe.w) > EPSF) ? qe.w : 1.0f;
            scale = 2.0f / dw;
        }
        float3 phi = make_float3(qe.x * scale, qe.y * scale, qe.z * scale);
        float theta = sqrtf(phi.x * phi.x + phi.y * phi.y + phi.z * phi.z);

        float c;
        if (theta < EPSF) {
            c = 1.0f / 12.0f;
        } else {
            float sth, cth;
            sincosf(theta, &sth, &cth);
            c = 1.0f / (theta * theta) - (1.0f + cth) / (2.0f * theta * sth);
        }

        float3 pxt  = f3cross(phi, te);
        float3 ppxt = f3cross(phi, pxt);
        r0 = te.x - 0.5f * pxt.x + c * ppxt.x;
        r1 = te.y - 0.5f * pxt.y + c * ppxt.y;
        r2 = te.z - 0.5f * pxt.z + c * ppxt.z;
        r3 = phi.x; r4 = phi.y; r5 = phi.z;
    }
    __syncthreads();  // everyone done reading sbuf (poses) before reuse

    // ---- stage output and stream out vectorized ----
    if (valid) {
        sbuf[t * 6 + 0] = r0; sbuf[t * 6 + 1] = r1; sbuf[t * 6 + 2] = r2;
        sbuf[t * 6 + 3] = r3; sbuf[t * 6 + 4] = r4; sbuf[t * 6 + 5] = r5;
    }
    __syncthreads();

    if (full) {
        float4* O4 = (float4*)(out + (size_t)e0 * 6);  // 6144B/block, 16B aligned
        const float4* S4 = (const float4*)sbuf;
        int k0 = t;
        O4[k0] = S4[k0];
        int k1 = t + 256;
        if (k1 < 384) O4[k1] = S4[k1];
    } else {
        int nf = (n_edges - e0) * 6;
        for (int k = t; k < nf; k += 256) out[(size_t)e0 * 6 + k] = sbuf[k];
    }
}

extern "C" void kernel_launch(void* const* d_in, const int* in_sizes, int n_in,
                              void* d_out, int out_size)
{
    // Robust input identification by size: nodes is smallest, poses largest,
    // edges in between (6.4M i32 / 22.4M f32 / 0.7M f32 for the dataset shapes).
    int ie = 0, ip = 1, in_ = 2;
    {
        long s0 = in_sizes[0], s1 = in_sizes[1], s2 = in_sizes[2];
        // smallest -> nodes
        in_ = (s0 <= s1 && s0 <= s2) ? 0 : (s1 <= s0 && s1 <= s2) ? 1 : 2;
        // largest -> poses
        ip  = (s0 >= s1 && s0 >= s2) ? 0 : (s1 >= s0 && s1 >= s2) ? 1 : 2;
        // remaining -> edges
        ie  = 3 - in_ - ip;
    }

    const int*   edges = (const int*)d_in[ie];
    const float* poses = (const float*)d_in[ip];
    const float* nodes = (const float*)d_in[in_];
    float*       out   = (float*)d_out;

    int n_edges = in_sizes[ie] / 2;
    int n_nodes = in_sizes[in_] / 7;
    if (n_nodes > 131072) n_nodes = 131072;  // static scratch bound

    pad_nodes_kernel<<<(n_nodes + 255) / 256, 256>>>(nodes, n_nodes);
    int blocks = (n_edges + 255) / 256;
    pose_graph_kernel<<<blocks, 256>>>(edges, poses, out, n_edges, n_nodes);
}

// round 4
// speedup vs baseline: 1.1866x; 1.1866x over previous
#include <cuda_runtime.h>
#include <cstdint>
#include <math.h>

#define EPSF 1e-6f

// Padded node table: up to 131072 nodes * 2 float4 = 4 MB static scratch.
__device__ float4 g_npad[131072 * 2];

__global__ void pad_nodes_kernel(const float* __restrict__ nodes, int n_nodes) {
    int i = blockIdx.x * blockDim.x + threadIdx.x;
    if (i < n_nodes) {
        const float* p = nodes + (size_t)i * 7;
        g_npad[i * 2 + 0] = make_float4(p[0], p[1], p[2], p[3]);
        g_npad[i * 2 + 1] = make_float4(p[4], p[5], p[6], 0.0f);
    }
}

__device__ __forceinline__ uint32_t smem_u32(const void* p) {
    return (uint32_t)__cvta_generic_to_shared(p);
}
__device__ __forceinline__ void cp16(uint32_t dst, const void* src) {
    asm volatile("cp.async.cg.shared.global [%0], [%1], 16;" :: "r"(dst), "l"(src));
}
__device__ __forceinline__ void cp_commit_wait() {
    asm volatile("cp.async.commit_group;\n\tcp.async.wait_group 0;" ::: "memory");
}

__device__ __forceinline__ float3 f3cross(float3 a, float3 b) {
    return make_float3(a.y * b.z - a.z * b.y,
                       a.z * b.x - a.x * b.z,
                       a.x * b.y - a.y * b.x);
}

__device__ __forceinline__ float3 qrot(float4 q, float3 v) {
    float3 u = make_float3(q.x, q.y, q.z);
    float3 t = f3cross(u, v);
    t.x *= 2.0f; t.y *= 2.0f; t.z *= 2.0f;
    float3 c = f3cross(u, t);
    return make_float3(v.x + q.w * t.x + c.x,
                       v.y + q.w * t.y + c.y,
                       v.z + q.w * t.z + c.z);
}

__device__ __forceinline__ float4 qmul(float4 a, float4 b) {
    return make_float4(
        a.w * b.x + a.x * b.w + a.y * b.z - a.z * b.y,
        a.w * b.y - a.x * b.z + a.y * b.w + a.z * b.x,
        a.w * b.z + a.x * b.y - a.y * b.x + a.z * b.w,
        a.w * b.w - a.x * b.x - a.y * b.y - a.z * b.z);
}

// Full per-edge SE(3) relative-pose error + log map.
__device__ __forceinline__ void edge_error(
    float p0, float p1, float p2, float p3, float p4, float p5, float p6,
    float4 n1a, float4 n1b, float4 n2a, float4 n2b,
    float& r0, float& r1, float& r2, float& r3, float& r4, float& r5)
{
    float3 t1 = make_float3(n1a.x, n1a.y, n1a.z);
    float4 q1 = make_float4(n1a.w, n1b.x, n1b.y, n1b.z);
    float3 t2 = make_float3(n2a.x, n2a.y, n2a.z);
    float4 q2 = make_float4(n2a.w, n2b.x, n2b.y, n2b.z);

    // A = inv(pose)
    float4 qa = make_float4(-p3, -p4, -p5, p6);
    float3 tp = make_float3(p0, p1, p2);
    float3 ra = qrot(qa, tp);
    float3 ta = make_float3(-ra.x, -ra.y, -ra.z);

    // B = A * node2
    float3 rb = qrot(qa, t2);
    float3 tb = make_float3(ta.x + rb.x, ta.y + rb.y, ta.z + rb.z);
    float4 qb = qmul(qa, q2);

    // C = inv(node1)
    float4 qc = make_float4(-q1.x, -q1.y, -q1.z, q1.w);
    float3 rc = qrot(qc, t1);
    float3 tc = make_float3(-rc.x, -rc.y, -rc.z);

    // E = B * C
    float3 re = qrot(qb, tc);
    float3 te = make_float3(tb.x + re.x, tb.y + re.y, tb.z + re.z);
    float4 qe = qmul(qb, qc);

    // se3_log using |qe| == 1:
    //   theta = 2*atan2(nn, w);  (1+cos th)/(2 sin th) == w/(2 nn)  exactly
    float nn2 = qe.x * qe.x + qe.y * qe.y + qe.z * qe.z;
    float nn  = sqrtf(nn2);
    float theta, scale;
    if (nn > EPSF) {
        theta = 2.0f * atan2f(nn, qe.w);
        scale = __fdividef(theta, nn);
    } else {
        float dw = (fabsf(qe.w) > EPSF) ? qe.w : 1.0f;
        scale = __fdividef(2.0f, dw);
        theta = fabsf(scale) * nn;   // tiny
    }
    float c;
    if (theta < EPSF) {
        c = 1.0f / 12.0f;
    } else {
        c = __fdividef(1.0f, theta * theta)
          - qe.w * __fdividef(0.5f, nn * theta);
    }

    float3 phi = make_float3(qe.x * scale, qe.y * scale, qe.z * scale);
    float3 pxt  = f3cross(phi, te);
    float3 ppxt = f3cross(phi, pxt);
    r0 = te.x - 0.5f * pxt.x + c * ppxt.x;
    r1 = te.y - 0.5f * pxt.y + c * ppxt.y;
    r2 = te.z - 0.5f * pxt.z + c * ppxt.z;
    r3 = phi.x; r4 = phi.y; r5 = phi.z;
}

__global__ __launch_bounds__(256)
void pose_graph_kernel(const int* __restrict__ edges,
                       const float* __restrict__ poses,
                       float* __restrict__ out,
                       int n_edges, int n_nodes)
{
    __shared__ float4 s0[512];       // per-warp 64 slots: first 16B of gathered node
    __shared__ float4 s1[512];       // second 16B
    __shared__ float  sp[8][224];    // pose staging: 32 edges * 7 floats per warp
    __shared__ float  so[8][192];    // output SoA: 6 comps * 32 edges per warp

    const int warp = threadIdx.x >> 5;
    const int lane = threadIdx.x & 31;
    const int ew0  = blockIdx.x * 256 + warp * 32;   // first edge of this warp
    const int e    = ew0 + lane;

    if (ew0 + 32 <= n_edges) {
        // ================= fast, warp-autonomous path =================
        int2 vi = __ldg((const int2*)edges + e);
        int i1 = min(max(vi.x, 0), n_nodes - 1);
        int i2 = min(max(vi.y, 0), n_nodes - 1);

        // stage poses: 56 float4 per warp, cp.async (L1-bypassing)
        const float4* P4 = (const float4*)(poses + (size_t)ew0 * 7);
        uint32_t spA = smem_u32(&sp[warp][0]);
        cp16(spA + lane * 16, P4 + lane);
        if (lane < 24) cp16(spA + (32 + lane) * 16, P4 + 32 + lane);

        // gather: 64 node-halves per warp; idx redistributed via shfl
        uint32_t s0A = smem_u32(&s0[warp * 64]);
        uint32_t s1A = smem_u32(&s1[warp * 64]);
        const int h  = lane & 1;       // which 16B half this lane fetches
        const int nl = lane >> 1;      // node-slot sub-index 0..15
        uint32_t dstBase = (h ? s1A : s0A);
#pragma unroll
        for (int j = 0; j < 4; j++) {
            int srcLane = ((j & 1) << 4) | nl;
            int idx = __shfl_sync(0xffffffffu, (j < 2) ? i1 : i2, srcLane);
            int n = j * 16 + nl;       // slots 0..31 = node1, 32..63 = node2
            cp16(dstBase + n * 16, &g_npad[idx * 2 + h]);
        }
        cp_commit_wait();
        __syncwarp();

        float p0 = sp[warp][lane * 7 + 0], p1 = sp[warp][lane * 7 + 1];
        float p2 = sp[warp][lane * 7 + 2], p3 = sp[warp][lane * 7 + 3];
        float p4 = sp[warp][lane * 7 + 4], p5 = sp[warp][lane * 7 + 5];
        float p6 = sp[warp][lane * 7 + 6];
        float4 n1a = s0[warp * 64 + lane],      n1b = s1[warp * 64 + lane];
        float4 n2a = s0[warp * 64 + 32 + lane], n2b = s1[warp * 64 + 32 + lane];

        float r0, r1, r2, r3, r4, r5;
        edge_error(p0, p1, p2, p3, p4, p5, p6, n1a, n1b, n2a, n2b,
                   r0, r1, r2, r3, r4, r5);

        // SoA staging (conflict-free STS)
        so[warp][0 * 32 + lane] = r0;
        so[warp][1 * 32 + lane] = r1;
        so[warp][2 * 32 + lane] = r2;
        so[warp][3 * 32 + lane] = r3;
        so[warp][4 * 32 + lane] = r4;
        so[warp][5 * 32 + lane] = r5;
        __syncwarp();

        // vectorized writeback: 48 float4 per warp
        float4* O4 = (float4*)(out + (size_t)ew0 * 6);
#pragma unroll
        for (int rep = 0; rep < 2; rep++) {
            int v = rep * 32 + lane;
            if (rep == 0 || lane < 16) {
                int f = 4 * v;
                float a0 = so[warp][((f    ) % 6) * 32 + ((f    ) / 6)];
                float a1 = so[warp][((f + 1) % 6) * 32 + ((f + 1) / 6)];
                float a2 = so[warp][((f + 2) % 6) * 32 + ((f + 2) / 6)];
                float a3 = so[warp][((f + 3) % 6) * 32 + ((f + 3) / 6)];
                O4[v] = make_float4(a0, a1, a2, a3);
            }
        }
    } else if (e < n_edges) {
        // ================= scalar tail path =================
        int2 vi = __ldg((const int2*)edges + e);
        int i1 = min(max(vi.x, 0), n_nodes - 1);
        int i2 = min(max(vi.y, 0), n_nodes - 1);
        const float* P = poses + (size_t)e * 7;
        float4 n1a = __ldg(&g_npad[i1 * 2 + 0]), n1b = __ldg(&g_npad[i1 * 2 + 1]);
        float4 n2a = __ldg(&g_npad[i2 * 2 + 0]), n2b = __ldg(&g_npad[i2 * 2 + 1]);
        float r0, r1, r2, r3, r4, r5;
        edge_error(P[0], P[1], P[2], P[3], P[4], P[5], P[6],
                   n1a, n1b, n2a, n2b, r0, r1, r2, r3, r4, r5);
        float* O = out + (size_t)e * 6;
        O[0] = r0; O[1] = r1; O[2] = r2; O[3] = r3; O[4] = r4; O[5] = r5;
    }
}

extern "C" void kernel_launch(void* const* d_in, const int* in_sizes, int n_in,
                              void* d_out, int out_size)
{
    // Identify inputs by size: nodes smallest, poses largest, edges remaining.
    int ie = 0, ip = 1, in_ = 2;
    {
        long s0 = in_sizes[0], s1 = in_sizes[1], s2 = in_sizes[2];
        in_ = (s0 <= s1 && s0 <= s2) ? 0 : (s1 <= s0 && s1 <= s2) ? 1 : 2;
        ip  = (s0 >= s1 && s0 >= s2) ? 0 : (s1 >= s0 && s1 >= s2) ? 1 : 2;
        ie  = 3 - in_ - ip;
    }

    const int*   edges = (const int*)d_in[ie];
    const float* poses = (const float*)d_in[ip];
    const float* nodes = (const float*)d_in[in_];
    float*       out   = (float*)d_out;

    int n_edges = in_sizes[ie] / 2;
    int n_nodes = in_sizes[in_] / 7;
    if (n_nodes > 131072) n_nodes = 131072;  // static scratch bound

    pad_nodes_kernel<<<(n_nodes + 255) / 256, 256>>>(nodes, n_nodes);
    int blocks = (n_edges + 255) / 256;
    pose_graph_kernel<<<blocks, 256>>>(edges, poses, out, n_edges, n_nodes);
}